// round 16
// baseline (speedup 1.0000x reference)
#include <cuda_runtime.h>
#include <cuda_fp16.h>
#include <cuda_bf16.h>
#include <math.h>

// Problem constants (fixed shapes per reference)
#define N_TOK   4096
#define D_EMB   1024
#define N_HEADS 16
#define D_HEAD  64
#define D3      (3 * D_EMB)   // 3072
#define N_GRAPHS 16

#define TQ 128
#define TK 64
#define MAX_TILES 48   // sum ceil(len/128) <= 4096/128 + 16

// ---------------- scratch (no allocation allowed) ----------------
__device__ __half g_qkvh[N_TOK * D3];      // qkv, fp16
__device__ __half g_attnh[N_TOK * D_EMB];  // attention output, fp16
__device__ __half g_xh[N_TOK * D_EMB];     // x, fp16
__device__ __half g_wih[D_EMB * D3];       // W_in, fp16  [K][N]
__device__ __half g_woh[D_EMB * D_EMB];    // W_out, fp16 [K][N]
__device__ int    g_batch[N_TOK];
__device__ int    g_seg[N_GRAPHS + 1];
__device__ int    g_tile_seg[MAX_TILES];
__device__ int    g_tile_q0[MAX_TILES];
__device__ int    g_ntiles;

// ---------------- prep ----------------
__global__ void prep_kernel(const void* __restrict__ batch_raw) {
    const int* w32 = (const int*)batch_raw;
    const bool is32 = (w32[N_TOK - 1] != 0);
    for (int i = threadIdx.x; i < N_TOK; i += blockDim.x) {
        int v;
        if (is32) v = w32[i];
        else      v = (int)((const long long*)batch_raw)[i];
        g_batch[i] = v;
    }
    __syncthreads();
    int g = threadIdx.x;
    if (g <= N_GRAPHS) {
        int lo = 0, hi = N_TOK;
        while (lo < hi) {
            int mid = (lo + hi) >> 1;
            if (g_batch[mid] < g) lo = mid + 1; else hi = mid;
        }
        g_seg[g] = lo;
    }
    __syncthreads();
    if (threadIdx.x == 0) {
        int cnt = 0;
        for (int s = 0; s < N_GRAPHS; s++)
            for (int q = g_seg[s]; q < g_seg[s + 1]; q += TQ) {
                g_tile_seg[cnt] = s;
                g_tile_q0[cnt]  = q;
                cnt++;
            }
        g_ntiles = cnt;
    }
}

// ---------------- helpers ----------------
__device__ __forceinline__ void mma_f16(float* c, const unsigned* a, const unsigned* b) {
    asm volatile(
        "mma.sync.aligned.m16n8k16.row.col.f32.f16.f16.f32 "
        "{%0,%1,%2,%3}, {%4,%5,%6,%7}, {%8,%9}, {%0,%1,%2,%3};"
        : "+f"(c[0]), "+f"(c[1]), "+f"(c[2]), "+f"(c[3])
        : "r"(a[0]), "r"(a[1]), "r"(a[2]), "r"(a[3]),
          "r"(b[0]), "r"(b[1]));
}

__device__ __forceinline__ void cp_async16(unsigned smem_addr, const void* gptr) {
    asm volatile("cp.async.ca.shared.global [%0], [%1], 16;"
                 :: "r"(smem_addr), "l"(gptr));
}

__device__ __forceinline__ void ldm_x4(unsigned* r, unsigned addr) {
    asm volatile("ldmatrix.sync.aligned.m8n8.x4.shared.b16 {%0,%1,%2,%3}, [%4];"
                 : "=r"(r[0]), "=r"(r[1]), "=r"(r[2]), "=r"(r[3]) : "r"(addr));
}

__device__ __forceinline__ void ldm_x4_t(unsigned* r, unsigned addr) {
    asm volatile("ldmatrix.sync.aligned.m8n8.x4.trans.shared.b16 {%0,%1,%2,%3}, [%4];"
                 : "=r"(r[0]), "=r"(r[1]), "=r"(r[2]), "=r"(r[3]) : "r"(addr));
}

// ---------------- fused fp32 -> fp16 conversion ----------------
__global__ void cvt_all_fp16(const float4* __restrict__ x,   uint2* __restrict__ xo,   int nx,
                             const float4* __restrict__ wi,  uint2* __restrict__ wio,  int nwi,
                             const float4* __restrict__ wo,  uint2* __restrict__ woo,  int nwo) {
    int i = blockIdx.x * blockDim.x + threadIdx.x;
    const float4* in;
    uint2* out;
    int j;
    if (i < nx)                 { in = x;  out = xo;  j = i; }
    else if (i < nx + nwi)      { in = wi; out = wio; j = i - nx; }
    else if (i < nx + nwi + nwo){ in = wo; out = woo; j = i - nx - nwi; }
    else return;
    float4 v = in[j];
    __half2 lo = __floats2half2_rn(v.x, v.y);
    __half2 hi = __floats2half2_rn(v.z, v.w);
    uint2 r;
    r.x = *reinterpret_cast<unsigned*>(&lo);
    r.y = *reinterpret_cast<unsigned*>(&hi);
    out[j] = r;
}

// ---------------- fp16 GEMM: block 128x256, warp 64x64, BK=64, 3-stage cp.async ----------------
#define A_STRIDE_B 144
#define B_STRIDE_B 528
#define A_BYTES (128 * A_STRIDE_B)   // 18432
#define B_BYTES (64 * B_STRIDE_B)    // 33792
#define NSTAGE 3
#define GEMM_SMEM (NSTAGE * (A_BYTES + B_BYTES))   // 156672

template <typename OutT>
__global__ __launch_bounds__(256, 1)
void gemm_f16_cp(int M, int N, int K,
                 const __half* __restrict__ A,
                 const __half* __restrict__ B,
                 const float* __restrict__ bias,
                 OutT* __restrict__ C)
{
    extern __shared__ char smem[];
    const unsigned s0 = (unsigned)__cvta_generic_to_shared(smem);
    unsigned aS[NSTAGE], bS[NSTAGE];
    #pragma unroll
    for (int s = 0; s < NSTAGE; s++) {
        aS[s] = s0 + s * (A_BYTES + B_BYTES);
        bS[s] = aS[s] + A_BYTES;
    }

    const int tid  = threadIdx.x;
    const int warp = tid >> 5;
    const int lane = tid & 31;
    const int wm   = warp >> 2;
    const int wn   = warp & 3;
    const int bm   = blockIdx.y * 128;
    const int bn   = blockIdx.x * 256;

    const int ar  = tid >> 1;
    const int ac4 = (tid & 1) * 4;
    const int bkr = tid >> 2;
    const int bc  = tid & 3;

    const __half* aSrc = A + (size_t)(bm + ar) * K + ac4 * 8;
    const __half* bSrc = B + (size_t)bkr * N + bn;

    auto cp_tile = [&](int kt) {
        const int buf = kt % NSTAGE;
        const int k0 = kt << 6;
        const __half* as = aSrc + k0;
        #pragma unroll
        for (int j = 0; j < 4; j++)
            cp_async16(aS[buf] + (unsigned)(ar * A_STRIDE_B + (ac4 + j) * 16),
                       as + j * 8);
        const __half* bs = bSrc + (size_t)k0 * N;
        #pragma unroll
        for (int q = 0; q < 8; q++)
            cp_async16(bS[buf] + (unsigned)(bkr * B_STRIDE_B + (bc + 4 * q) * 16),
                       bs + (bc + 4 * q) * 8);
        asm volatile("cp.async.commit_group;");
    };

    float acc[4][8][4];
    #pragma unroll
    for (int i = 0; i < 4; i++)
        #pragma unroll
        for (int j = 0; j < 8; j++)
            #pragma unroll
            for (int r = 0; r < 4; r++) acc[i][j][r] = 0.f;

    const int lrow = lane & 15;
    const int lseg = lane >> 4;

    const int KT = K >> 6;
    cp_tile(0);
    if (KT > 1) cp_tile(1);

    for (int kt = 0; kt < KT; kt++) {
        const int buf = kt % NSTAGE;
        // ensure tile kt landed: allow (groups issued after kt) to stay outstanding
        if (kt + 1 < KT) asm volatile("cp.async.wait_group 1;");
        else             asm volatile("cp.async.wait_group 0;");
        __syncthreads();
        if (kt + 2 < KT) cp_tile(kt + 2);   // buffer of kt-1, freed by the sync above

        #pragma unroll
        for (int kb = 0; kb < 4; kb++) {
            unsigned afr[4][4], bfr[4][4];
            #pragma unroll
            for (int i = 0; i < 4; i++) {
                const unsigned ad = aS[buf]
                    + (unsigned)((wm * 64 + i * 16 + lrow) * A_STRIDE_B
                                 + kb * 32 + lseg * 16);
                ldm_x4(afr[i], ad);
            }
            #pragma unroll
            for (int j = 0; j < 4; j++) {
                const unsigned bd = bS[buf]
                    + (unsigned)((kb * 16 + lrow) * B_STRIDE_B
                                 + wn * 128 + j * 32 + lseg * 16);
                ldm_x4_t(bfr[j], bd);
            }
            #pragma unroll
            for (int i = 0; i < 4; i++)
                #pragma unroll
                for (int j8 = 0; j8 < 8; j8++)
                    mma_f16(acc[i][j8], afr[i], &bfr[j8 >> 1][(j8 & 1) * 2]);
        }
        __syncthreads();
    }

    // epilogue: bias + store
    const int lg = lane >> 2;
    const int lc = lane & 3;
    #pragma unroll
    for (int i = 0; i < 4; i++) {
        const int m0 = bm + wm * 64 + i * 16 + lg;
        #pragma unroll
        for (int j = 0; j < 8; j++) {
            const int n0 = bn + wn * 64 + j * 8 + lc * 2;
            const float bx = bias[n0];
            const float by = bias[n0 + 1];
            if constexpr (sizeof(OutT) == 4) {
                float2 v0 = make_float2(acc[i][j][0] + bx, acc[i][j][1] + by);
                float2 v1 = make_float2(acc[i][j][2] + bx, acc[i][j][3] + by);
                *reinterpret_cast<float2*>((float*)C + (size_t)m0 * N + n0)       = v0;
                *reinterpret_cast<float2*>((float*)C + (size_t)(m0 + 8) * N + n0) = v1;
            } else {
                __half2 v0 = __floats2half2_rn(acc[i][j][0] + bx, acc[i][j][1] + by);
                __half2 v1 = __floats2half2_rn(acc[i][j][2] + bx, acc[i][j][3] + by);
                *reinterpret_cast<__half2*>((__half*)C + (size_t)m0 * N + n0)       = v0;
                *reinterpret_cast<__half2*>((__half*)C + (size_t)(m0 + 8) * N + n0) = v1;
            }
        }
    }
}

// ---------------- fp16 tensor-core flash attention: TQ=128, 8 warps ----------------
#define AQ_STR 72   // halves per row = 144 B
// smem: Q 128 rows + K 64 + P 128 + V 64 = 384 rows
#define ATTN_SMEM (384 * AQ_STR * 2)

__global__ __launch_bounds__(256)
void attn_f16(const __half* __restrict__ qkv, __half* __restrict__ out)
{
    const int tile = blockIdx.x;
    if (tile >= g_ntiles) return;
    const int h   = blockIdx.y;
    const int seg = g_tile_seg[tile];
    const int q0  = g_tile_q0[tile];
    const int e   = g_seg[seg + 1];
    const int qlen = min(TQ, e - q0);

    extern __shared__ __half smh[];
    __half* Qs = smh;                    // [128][AQ_STR]
    __half* Ks = Qs + 128 * AQ_STR;      // [64][AQ_STR]
    __half* Ps = Ks + 64 * AQ_STR;       // [128][AQ_STR]
    __half* Vs = Ps + 128 * AQ_STR;      // [64][AQ_STR]

    const unsigned qB = (unsigned)__cvta_generic_to_shared(Qs);
    const unsigned kB = (unsigned)__cvta_generic_to_shared(Ks);
    const unsigned pB = (unsigned)__cvta_generic_to_shared(Ps);
    const unsigned vB = (unsigned)__cvta_generic_to_shared(Vs);

    const int tid  = threadIdx.x;
    const int warp = tid >> 5;           // 0..7, owns q-rows 16w..16w+15
    const int lane = tid & 31;
    const int lq   = lane >> 2;
    const int kc   = lane & 3;
    const int lrow = lane & 15;
    const int lseg = lane >> 4;

    // ---- load Q: 128 rows x 8 chunks = 1024 chunks over 256 threads ----
    #pragma unroll
    for (int c = tid; c < 1024; c += 256) {
        const int row = c >> 3, ch = c & 7;
        uint4 v = (row < qlen)
            ? *reinterpret_cast<const uint4*>(qkv + (size_t)(q0 + row) * D3 + h * D_HEAD + ch * 8)
            : make_uint4(0, 0, 0, 0);
        *reinterpret_cast<uint4*>(&Qs[row * AQ_STR + ch * 8]) = v;
    }

    const int r0 = warp * 16 + lq;

    float m0 = -INFINITY, m1 = -INFINITY, l0 = 0.f, l1 = 0.f;
    float oacc[8][4];
    #pragma unroll
    for (int nb = 0; nb < 8; nb++)
        #pragma unroll
        for (int r = 0; r < 4; r++) oacc[nb][r] = 0.f;

    for (int mm0 = g_seg[seg]; mm0 < e; mm0 += TK) {
        const int klen = min(TK, e - mm0);
        __syncthreads();

        // ---- load K, V: 64 rows x 8 chunks = 512 chunks over 256 threads ----
        #pragma unroll
        for (int c = tid; c < 512; c += 256) {
            const int row = c >> 3, ch = c & 7;
            const bool valid = (row < klen);
            uint4 kv = valid
                ? *reinterpret_cast<const uint4*>(qkv + (size_t)(mm0 + row) * D3 + D_EMB + h * D_HEAD + ch * 8)
                : make_uint4(0, 0, 0, 0);
            *reinterpret_cast<uint4*>(&Ks[row * AQ_STR + ch * 8]) = kv;
            uint4 vv = valid
                ? *reinterpret_cast<const uint4*>(qkv + (size_t)(mm0 + row) * D3 + 2 * D_EMB + h * D_HEAD + ch * 8)
                : make_uint4(0, 0, 0, 0);
            *reinterpret_cast<uint4*>(&Vs[row * AQ_STR + ch * 8]) = vv;
        }
        __syncthreads();

        // ---- S = Q @ K^T ----
        unsigned aq[4][4];
        #pragma unroll
        for (int kb = 0; kb < 4; kb++)
            ldm_x4(aq[kb], qB + (unsigned)(((warp * 16 + lrow) * AQ_STR + kb * 16 + lseg * 8) * 2));

        float sacc[8][4];
        #pragma unroll
        for (int nb = 0; nb < 8; nb++)
            #pragma unroll
            for (int r = 0; r < 4; r++) sacc[nb][r] = 0.f;

        #pragma unroll
        for (int kb = 0; kb < 4; kb++) {
            #pragma unroll
            for (int nbb = 0; nbb < 4; nbb++) {
                unsigned bk[4];
                ldm_x4(bk, kB + (unsigned)(((nbb * 16 + lrow) * AQ_STR + kb * 16 + lseg * 8) * 2));
                unsigned b0[2] = { bk[0], bk[2] };
                unsigned b1[2] = { bk[1], bk[3] };
                mma_f16(sacc[2 * nbb],     aq[kb], b0);
                mma_f16(sacc[2 * nbb + 1], aq[kb], b1);
            }
        }

        // ---- online softmax (fp32) ----
        float rmax0 = -INFINITY, rmax1 = -INFINITY;
        #pragma unroll
        for (int nb = 0; nb < 8; nb++) {
            #pragma unroll
            for (int r = 0; r < 4; r++) {
                const int col = nb * 8 + 2 * kc + (r & 1);
                float s = (col < klen) ? sacc[nb][r] * 0.125f : -INFINITY;
                sacc[nb][r] = s;
                if (r < 2) rmax0 = fmaxf(rmax0, s);
                else       rmax1 = fmaxf(rmax1, s);
            }
        }
        #pragma unroll
        for (int o = 1; o < 4; o <<= 1) {
            rmax0 = fmaxf(rmax0, __shfl_xor_sync(0xffffffffu, rmax0, o));
            rmax1 = fmaxf(rmax1, __shfl_xor_sync(0xffffffffu, rmax1, o));
        }
        const float mn0 = fmaxf(m0, rmax0);
        const float mn1 = fmaxf(m1, rmax1);
        const float corr0 = __expf(m0 - mn0);
        const float corr1 = __expf(m1 - mn1);
        float rsum0 = 0.f, rsum1 = 0.f;
        #pragma unroll
        for (int nb = 0; nb < 8; nb++) {
            const int cb = nb * 8 + 2 * kc;
            float p0 = __expf(sacc[nb][0] - mn0);
            float p1 = __expf(sacc[nb][1] - mn0);
            float p2 = __expf(sacc[nb][2] - mn1);
            float p3 = __expf(sacc[nb][3] - mn1);
            rsum0 += p0 + p1;
            rsum1 += p2 + p3;
            *reinterpret_cast<__half2*>(&Ps[r0 * AQ_STR + cb])       = __floats2half2_rn(p0, p1);
            *reinterpret_cast<__half2*>(&Ps[(r0 + 8) * AQ_STR + cb]) = __floats2half2_rn(p2, p3);
        }
        #pragma unroll
        for (int o = 1; o < 4; o <<= 1) {
            rsum0 += __shfl_xor_sync(0xffffffffu, rsum0, o);
            rsum1 += __shfl_xor_sync(0xffffffffu, rsum1, o);
        }
        l0 = l0 * corr0 + rsum0;
        l1 = l1 * corr1 + rsum1;
        m0 = mn0;
        m1 = mn1;
        #pragma unroll
        for (int nb = 0; nb < 8; nb++) {
            oacc[nb][0] *= corr0;
            oacc[nb][1] *= corr0;
            oacc[nb][2] *= corr1;
            oacc[nb][3] *= corr1;
        }
        __syncwarp();   // warp reads back only its own P rows

        // ---- O += P @ V ----
        unsigned ap[4][4];
        #pragma unroll
        for (int kb = 0; kb < 4; kb++)
            ldm_x4(ap[kb], pB + (unsigned)(((warp * 16 + lrow) * AQ_STR + kb * 16 + lseg * 8) * 2));

        #pragma unroll
        for (int kb = 0; kb < 4; kb++) {
            #pragma unroll
            for (int j = 0; j < 4; j++) {
                unsigned bv[4];
                ldm_x4_t(bv, vB + (unsigned)(((kb * 16 + lrow) * AQ_STR + j * 16 + lseg * 8) * 2));
                mma_f16(oacc[2 * j],     ap[kb], &bv[0]);
                mma_f16(oacc[2 * j + 1], ap[kb], &bv[2]);
            }
        }
    }

    // ---- write O (fp16 for GEMM2) ----
    const float inv0 = 1.f / l0;
    const float inv1 = 1.f / l1;
    #pragma unroll
    for (int nb = 0; nb < 8; nb++) {
        const int col = nb * 8 + 2 * kc;
        if (r0 < qlen) {
            __half2 v = __floats2half2_rn(oacc[nb][0] * inv0, oacc[nb][1] * inv0);
            *reinterpret_cast<__half2*>(
                out + (size_t)(q0 + r0) * D_EMB + h * D_HEAD + col) = v;
        }
        if (r0 + 8 < qlen) {
            __half2 v = __floats2half2_rn(oacc[nb][2] * inv1, oacc[nb][3] * inv1);
            *reinterpret_cast<__half2*>(
                out + (size_t)(q0 + r0 + 8) * D_EMB + h * D_HEAD + col) = v;
        }
    }
}

// ---------------- launcher ----------------
extern "C" void kernel_launch(void* const* d_in, const int* in_sizes, int n_in,
                              void* d_out, int out_size)
{
    const float* x     = (const float*)d_in[0];
    const void*  batch = d_in[1];
    const float* W_in  = (const float*)d_in[2];
    const float* b_in  = (const float*)d_in[3];
    const float* W_out = (const float*)d_in[4];
    const float* b_out = (const float*)d_in[5];
    float*       out   = (float*)d_out;

    __half* qkvh;  cudaGetSymbolAddress((void**)&qkvh,  g_qkvh);
    __half* attnh; cudaGetSymbolAddress((void**)&attnh, g_attnh);
    __half* xh;    cudaGetSymbolAddress((void**)&xh,    g_xh);
    __half* wih;   cudaGetSymbolAddress((void**)&wih,   g_wih);
    __half* woh;   cudaGetSymbolAddress((void**)&woh,   g_woh);

    cudaFuncSetAttribute(gemm_f16_cp<__half>,
                         cudaFuncAttributeMaxDynamicSharedMemorySize, GEMM_SMEM);
    cudaFuncSetAttribute(gemm_f16_cp<float>,
                         cudaFuncAttributeMaxDynamicSharedMemorySize, GEMM_SMEM);
    cudaFuncSetAttribute(attn_f16,
                         cudaFuncAttributeMaxDynamicSharedMemorySize, ATTN_SMEM);

    prep_kernel<<<1, 256>>>(batch);

    // fused fp16 conversion (single launch)
    {
        const int nx  = (N_TOK * D_EMB) / 4;
        const int nwi = (D_EMB * D3) / 4;
        const int nwo = (D_EMB * D_EMB) / 4;
        const int tot = nx + nwi + nwo;
        cvt_all_fp16<<<(tot + 255) / 256, 256>>>(
            (const float4*)x,     (uint2*)xh,  nx,
            (const float4*)W_in,  (uint2*)wih, nwi,
            (const float4*)W_out, (uint2*)woh, nwo);
    }

    {   // qkv = x @ W_in + b_in   (fp16 in, fp16 out)
        dim3 grid(D3 / 256, N_TOK / 128);
        gemm_f16_cp<__half><<<grid, 256, GEMM_SMEM>>>(N_TOK, D3, D_EMB, xh, wih, b_in, qkvh);
    }

    {   // segment-local fp16 tensor-core attention (TQ=128)
        dim3 grid(MAX_TILES, N_HEADS);
        attn_f16<<<grid, 256, ATTN_SMEM>>>(qkvh, attnh);
    }

    {   // out = attn @ W_out + b_out  (fp32 out)
        dim3 grid(D_EMB / 256, N_TOK / 128);
        gemm_f16_cp<float><<<grid, 256, GEMM_SMEM>>>(N_TOK, D_EMB, D_EMB, attnh, woh, b_out, out);
    }
}

// round 17
// speedup vs baseline: 1.0015x; 1.0015x over previous
#include <cuda_runtime.h>
#include <cuda_fp16.h>
#include <cuda_bf16.h>
#include <math.h>

// Problem constants (fixed shapes per reference)
#define N_TOK   4096
#define D_EMB   1024
#define N_HEADS 16
#define D_HEAD  64
#define D3      (3 * D_EMB)   // 3072
#define N_GRAPHS 16

#define TQ 128
#define TK 64
#define MAX_TILES 48   // sum ceil(len/128) <= 4096/128 + 16

// ---------------- scratch (no allocation allowed) ----------------
__device__ __half g_qkvh[N_TOK * D3];      // qkv, fp16
__device__ __half g_attnh[N_TOK * D_EMB];  // attention output, fp16
__device__ __half g_xh[N_TOK * D_EMB];     // x, fp16
__device__ __half g_wih[D_EMB * D3];       // W_in, fp16  [K][N]
__device__ __half g_woh[D_EMB * D_EMB];    // W_out, fp16 [K][N]
__device__ int    g_batch[N_TOK];
__device__ int    g_seg[N_GRAPHS + 1];
__device__ int    g_tile_seg[MAX_TILES];
__device__ int    g_tile_q0[MAX_TILES];
__device__ int    g_ntiles;

// ---------------- prep ----------------
__global__ void prep_kernel(const void* __restrict__ batch_raw) {
    const int* w32 = (const int*)batch_raw;
    const bool is32 = (w32[N_TOK - 1] != 0);
    for (int i = threadIdx.x; i < N_TOK; i += blockDim.x) {
        int v;
        if (is32) v = w32[i];
        else      v = (int)((const long long*)batch_raw)[i];
        g_batch[i] = v;
    }
    __syncthreads();
    int g = threadIdx.x;
    if (g <= N_GRAPHS) {
        int lo = 0, hi = N_TOK;
        while (lo < hi) {
            int mid = (lo + hi) >> 1;
            if (g_batch[mid] < g) lo = mid + 1; else hi = mid;
        }
        g_seg[g] = lo;
    }
    __syncthreads();
    if (threadIdx.x == 0) {
        int cnt = 0;
        for (int s = 0; s < N_GRAPHS; s++)
            for (int q = g_seg[s]; q < g_seg[s + 1]; q += TQ) {
                g_tile_seg[cnt] = s;
                g_tile_q0[cnt]  = q;
                cnt++;
            }
        g_ntiles = cnt;
    }
}

// ---------------- helpers ----------------
__device__ __forceinline__ void mma_f16(float* c, const unsigned* a, const unsigned* b) {
    asm volatile(
        "mma.sync.aligned.m16n8k16.row.col.f32.f16.f16.f32 "
        "{%0,%1,%2,%3}, {%4,%5,%6,%7}, {%8,%9}, {%0,%1,%2,%3};"
        : "+f"(c[0]), "+f"(c[1]), "+f"(c[2]), "+f"(c[3])
        : "r"(a[0]), "r"(a[1]), "r"(a[2]), "r"(a[3]),
          "r"(b[0]), "r"(b[1]));
}

__device__ __forceinline__ void cp_async16(unsigned smem_addr, const void* gptr) {
    asm volatile("cp.async.ca.shared.global [%0], [%1], 16;"
                 :: "r"(smem_addr), "l"(gptr));
}

__device__ __forceinline__ void ldm_x4(unsigned* r, unsigned addr) {
    asm volatile("ldmatrix.sync.aligned.m8n8.x4.shared.b16 {%0,%1,%2,%3}, [%4];"
                 : "=r"(r[0]), "=r"(r[1]), "=r"(r[2]), "=r"(r[3]) : "r"(addr));
}

__device__ __forceinline__ void ldm_x4_t(unsigned* r, unsigned addr) {
    asm volatile("ldmatrix.sync.aligned.m8n8.x4.trans.shared.b16 {%0,%1,%2,%3}, [%4];"
                 : "=r"(r[0]), "=r"(r[1]), "=r"(r[2]), "=r"(r[3]) : "r"(addr));
}

// ---------------- fused fp32 -> fp16 conversion ----------------
__global__ void cvt_all_fp16(const float4* __restrict__ x,   uint2* __restrict__ xo,   int nx,
                             const float4* __restrict__ wi,  uint2* __restrict__ wio,  int nwi,
                             const float4* __restrict__ wo,  uint2* __restrict__ woo,  int nwo) {
    int i = blockIdx.x * blockDim.x + threadIdx.x;
    const float4* in;
    uint2* out;
    int j;
    if (i < nx)                 { in = x;  out = xo;  j = i; }
    else if (i < nx + nwi)      { in = wi; out = wio; j = i - nx; }
    else if (i < nx + nwi + nwo){ in = wo; out = woo; j = i - nx - nwi; }
    else return;
    float4 v = in[j];
    __half2 lo = __floats2half2_rn(v.x, v.y);
    __half2 hi = __floats2half2_rn(v.z, v.w);
    uint2 r;
    r.x = *reinterpret_cast<unsigned*>(&lo);
    r.y = *reinterpret_cast<unsigned*>(&hi);
    out[j] = r;
}

// ---------------- fp16 GEMM: block 128x256, warp 64x64, BK=64, 3-stage cp.async ----------------
#define A_STRIDE_B 144
#define B_STRIDE_B 528
#define A_BYTES (128 * A_STRIDE_B)   // 18432
#define B_BYTES (64 * B_STRIDE_B)    // 33792
#define NSTAGE 3
#define GEMM_SMEM (NSTAGE * (A_BYTES + B_BYTES))   // 156672

template <typename OutT>
__global__ __launch_bounds__(256, 1)
void gemm_f16_cp(int M, int N, int K,
                 const __half* __restrict__ A,
                 const __half* __restrict__ B,
                 const float* __restrict__ bias,
                 OutT* __restrict__ C)
{
    extern __shared__ char smem[];
    const unsigned s0 = (unsigned)__cvta_generic_to_shared(smem);
    unsigned aS[NSTAGE], bS[NSTAGE];
    #pragma unroll
    for (int s = 0; s < NSTAGE; s++) {
        aS[s] = s0 + s * (A_BYTES + B_BYTES);
        bS[s] = aS[s] + A_BYTES;
    }

    const int tid  = threadIdx.x;
    const int warp = tid >> 5;
    const int lane = tid & 31;
    const int wm   = warp >> 2;
    const int wn   = warp & 3;
    const int bm   = blockIdx.y * 128;
    const int bn   = blockIdx.x * 256;

    const int ar  = tid >> 1;
    const int ac4 = (tid & 1) * 4;
    const int bkr = tid >> 2;
    const int bc  = tid & 3;

    const __half* aSrc = A + (size_t)(bm + ar) * K + ac4 * 8;
    const __half* bSrc = B + (size_t)bkr * N + bn;

    auto cp_tile = [&](int kt) {
        const int buf = kt % NSTAGE;
        const int k0 = kt << 6;
        const __half* as = aSrc + k0;
        #pragma unroll
        for (int j = 0; j < 4; j++)
            cp_async16(aS[buf] + (unsigned)(ar * A_STRIDE_B + (ac4 + j) * 16),
                       as + j * 8);
        const __half* bs = bSrc + (size_t)k0 * N;
        #pragma unroll
        for (int q = 0; q < 8; q++)
            cp_async16(bS[buf] + (unsigned)(bkr * B_STRIDE_B + (bc + 4 * q) * 16),
                       bs + (bc + 4 * q) * 8);
        asm volatile("cp.async.commit_group;");
    };

    float acc[4][8][4];
    #pragma unroll
    for (int i = 0; i < 4; i++)
        #pragma unroll
        for (int j = 0; j < 8; j++)
            #pragma unroll
            for (int r = 0; r < 4; r++) acc[i][j][r] = 0.f;

    const int lrow = lane & 15;
    const int lseg = lane >> 4;

    const int KT = K >> 6;
    cp_tile(0);
    if (KT > 1) cp_tile(1);

    for (int kt = 0; kt < KT; kt++) {
        const int buf = kt % NSTAGE;
        // ensure tile kt landed: allow (groups issued after kt) to stay outstanding
        if (kt + 1 < KT) asm volatile("cp.async.wait_group 1;");
        else             asm volatile("cp.async.wait_group 0;");
        __syncthreads();
        if (kt + 2 < KT) cp_tile(kt + 2);   // buffer of kt-1, freed by the sync above

        #pragma unroll
        for (int kb = 0; kb < 4; kb++) {
            unsigned afr[4][4], bfr[4][4];
            #pragma unroll
            for (int i = 0; i < 4; i++) {
                const unsigned ad = aS[buf]
                    + (unsigned)((wm * 64 + i * 16 + lrow) * A_STRIDE_B
                                 + kb * 32 + lseg * 16);
                ldm_x4(afr[i], ad);
            }
            #pragma unroll
            for (int j = 0; j < 4; j++) {
                const unsigned bd = bS[buf]
                    + (unsigned)((kb * 16 + lrow) * B_STRIDE_B
                                 + wn * 128 + j * 32 + lseg * 16);
                ldm_x4_t(bfr[j], bd);
            }
            #pragma unroll
            for (int i = 0; i < 4; i++)
                #pragma unroll
                for (int j8 = 0; j8 < 8; j8++)
                    mma_f16(acc[i][j8], afr[i], &bfr[j8 >> 1][(j8 & 1) * 2]);
        }
        __syncthreads();
    }

    // epilogue: bias + store
    const int lg = lane >> 2;
    const int lc = lane & 3;
    #pragma unroll
    for (int i = 0; i < 4; i++) {
        const int m0 = bm + wm * 64 + i * 16 + lg;
        #pragma unroll
        for (int j = 0; j < 8; j++) {
            const int n0 = bn + wn * 64 + j * 8 + lc * 2;
            const float bx = bias[n0];
            const float by = bias[n0 + 1];
            if constexpr (sizeof(OutT) == 4) {
                float2 v0 = make_float2(acc[i][j][0] + bx, acc[i][j][1] + by);
                float2 v1 = make_float2(acc[i][j][2] + bx, acc[i][j][3] + by);
                *reinterpret_cast<float2*>((float*)C + (size_t)m0 * N + n0)       = v0;
                *reinterpret_cast<float2*>((float*)C + (size_t)(m0 + 8) * N + n0) = v1;
            } else {
                __half2 v0 = __floats2half2_rn(acc[i][j][0] + bx, acc[i][j][1] + by);
                __half2 v1 = __floats2half2_rn(acc[i][j][2] + bx, acc[i][j][3] + by);
                *reinterpret_cast<__half2*>((__half*)C + (size_t)m0 * N + n0)       = v0;
                *reinterpret_cast<__half2*>((__half*)C + (size_t)(m0 + 8) * N + n0) = v1;
            }
        }
    }
}

// ---------------- fp16 tensor-core flash attention: TQ=128, 8 warps ----------------
#define AQ_STR 72   // halves per row = 144 B
// smem: Q 128 rows + K 64 + P 128 + V 64 = 384 rows
#define ATTN_SMEM (384 * AQ_STR * 2)

__global__ __launch_bounds__(256)
void attn_f16(const __half* __restrict__ qkv, __half* __restrict__ out)
{
    const int tile = blockIdx.x;
    if (tile >= g_ntiles) return;
    const int h   = blockIdx.y;
    const int seg = g_tile_seg[tile];
    const int q0  = g_tile_q0[tile];
    const int e   = g_seg[seg + 1];
    const int qlen = min(TQ, e - q0);

    extern __shared__ __half smh[];
    __half* Qs = smh;                    // [128][AQ_STR]
    __half* Ks = Qs + 128 * AQ_STR;      // [64][AQ_STR]
    __half* Ps = Ks + 64 * AQ_STR;       // [128][AQ_STR]
    __half* Vs = Ps + 128 * AQ_STR;      // [64][AQ_STR]

    const unsigned qB = (unsigned)__cvta_generic_to_shared(Qs);
    const unsigned kB = (unsigned)__cvta_generic_to_shared(Ks);
    const unsigned pB = (unsigned)__cvta_generic_to_shared(Ps);
    const unsigned vB = (unsigned)__cvta_generic_to_shared(Vs);

    const int tid  = threadIdx.x;
    const int warp = tid >> 5;           // 0..7, owns q-rows 16w..16w+15
    const int lane = tid & 31;
    const int lq   = lane >> 2;
    const int kc   = lane & 3;
    const int lrow = lane & 15;
    const int lseg = lane >> 4;

    // ---- load Q: 128 rows x 8 chunks = 1024 chunks over 256 threads ----
    #pragma unroll
    for (int c = tid; c < 1024; c += 256) {
        const int row = c >> 3, ch = c & 7;
        uint4 v = (row < qlen)
            ? *reinterpret_cast<const uint4*>(qkv + (size_t)(q0 + row) * D3 + h * D_HEAD + ch * 8)
            : make_uint4(0, 0, 0, 0);
        *reinterpret_cast<uint4*>(&Qs[row * AQ_STR + ch * 8]) = v;
    }

    const int r0 = warp * 16 + lq;

    float m0 = -INFINITY, m1 = -INFINITY, l0 = 0.f, l1 = 0.f;
    float oacc[8][4];
    #pragma unroll
    for (int nb = 0; nb < 8; nb++)
        #pragma unroll
        for (int r = 0; r < 4; r++) oacc[nb][r] = 0.f;

    for (int mm0 = g_seg[seg]; mm0 < e; mm0 += TK) {
        const int klen = min(TK, e - mm0);
        __syncthreads();

        // ---- load K, V: 64 rows x 8 chunks = 512 chunks over 256 threads ----
        #pragma unroll
        for (int c = tid; c < 512; c += 256) {
            const int row = c >> 3, ch = c & 7;
            const bool valid = (row < klen);
            uint4 kv = valid
                ? *reinterpret_cast<const uint4*>(qkv + (size_t)(mm0 + row) * D3 + D_EMB + h * D_HEAD + ch * 8)
                : make_uint4(0, 0, 0, 0);
            *reinterpret_cast<uint4*>(&Ks[row * AQ_STR + ch * 8]) = kv;
            uint4 vv = valid
                ? *reinterpret_cast<const uint4*>(qkv + (size_t)(mm0 + row) * D3 + 2 * D_EMB + h * D_HEAD + ch * 8)
                : make_uint4(0, 0, 0, 0);
            *reinterpret_cast<uint4*>(&Vs[row * AQ_STR + ch * 8]) = vv;
        }
        __syncthreads();

        // ---- S = Q @ K^T ----
        unsigned aq[4][4];
        #pragma unroll
        for (int kb = 0; kb < 4; kb++)
            ldm_x4(aq[kb], qB + (unsigned)(((warp * 16 + lrow) * AQ_STR + kb * 16 + lseg * 8) * 2));

        float sacc[8][4];
        #pragma unroll
        for (int nb = 0; nb < 8; nb++)
            #pragma unroll
            for (int r = 0; r < 4; r++) sacc[nb][r] = 0.f;

        #pragma unroll
        for (int kb = 0; kb < 4; kb++) {
            #pragma unroll
            for (int nbb = 0; nbb < 4; nbb++) {
                unsigned bk[4];
                ldm_x4(bk, kB + (unsigned)(((nbb * 16 + lrow) * AQ_STR + kb * 16 + lseg * 8) * 2));
                unsigned b0[2] = { bk[0], bk[2] };
                unsigned b1[2] = { bk[1], bk[3] };
                mma_f16(sacc[2 * nbb],     aq[kb], b0);
                mma_f16(sacc[2 * nbb + 1], aq[kb], b1);
            }
        }

        // ---- online softmax (fp32) ----
        float rmax0 = -INFINITY, rmax1 = -INFINITY;
        #pragma unroll
        for (int nb = 0; nb < 8; nb++) {
            #pragma unroll
            for (int r = 0; r < 4; r++) {
                const int col = nb * 8 + 2 * kc + (r & 1);
                float s = (col < klen) ? sacc[nb][r] * 0.125f : -INFINITY;
                sacc[nb][r] = s;
                if (r < 2) rmax0 = fmaxf(rmax0, s);
                else       rmax1 = fmaxf(rmax1, s);
            }
        }
        #pragma unroll
        for (int o = 1; o < 4; o <<= 1) {
            rmax0 = fmaxf(rmax0, __shfl_xor_sync(0xffffffffu, rmax0, o));
            rmax1 = fmaxf(rmax1, __shfl_xor_sync(0xffffffffu, rmax1, o));
        }
        const float mn0 = fmaxf(m0, rmax0);
        const float mn1 = fmaxf(m1, rmax1);
        const float corr0 = __expf(m0 - mn0);
        const float corr1 = __expf(m1 - mn1);
        float rsum0 = 0.f, rsum1 = 0.f;
        #pragma unroll
        for (int nb = 0; nb < 8; nb++) {
            const int cb = nb * 8 + 2 * kc;
            float p0 = __expf(sacc[nb][0] - mn0);
            float p1 = __expf(sacc[nb][1] - mn0);
            float p2 = __expf(sacc[nb][2] - mn1);
            float p3 = __expf(sacc[nb][3] - mn1);
            rsum0 += p0 + p1;
            rsum1 += p2 + p3;
            *reinterpret_cast<__half2*>(&Ps[r0 * AQ_STR + cb])       = __floats2half2_rn(p0, p1);
            *reinterpret_cast<__half2*>(&Ps[(r0 + 8) * AQ_STR + cb]) = __floats2half2_rn(p2, p3);
        }
        #pragma unroll
        for (int o = 1; o < 4; o <<= 1) {
            rsum0 += __shfl_xor_sync(0xffffffffu, rsum0, o);
            rsum1 += __shfl_xor_sync(0xffffffffu, rsum1, o);
        }
        l0 = l0 * corr0 + rsum0;
        l1 = l1 * corr1 + rsum1;
        m0 = mn0;
        m1 = mn1;
        #pragma unroll
        for (int nb = 0; nb < 8; nb++) {
            oacc[nb][0] *= corr0;
            oacc[nb][1] *= corr0;
            oacc[nb][2] *= corr1;
            oacc[nb][3] *= corr1;
        }
        __syncwarp();   // warp reads back only its own P rows

        // ---- O += P @ V ----
        unsigned ap[4][4];
        #pragma unroll
        for (int kb = 0; kb < 4; kb++)
            ldm_x4(ap[kb], pB + (unsigned)(((warp * 16 + lrow) * AQ_STR + kb * 16 + lseg * 8) * 2));

        #pragma unroll
        for (int kb = 0; kb < 4; kb++) {
            #pragma unroll
            for (int j = 0; j < 4; j++) {
                unsigned bv[4];
                ldm_x4_t(bv, vB + (unsigned)(((kb * 16 + lrow) * AQ_STR + j * 16 + lseg * 8) * 2));
                mma_f16(oacc[2 * j],     ap[kb], &bv[0]);
                mma_f16(oacc[2 * j + 1], ap[kb], &bv[2]);
            }
        }
    }

    // ---- write O (fp16 for GEMM2) ----
    const float inv0 = 1.f / l0;
    const float inv1 = 1.f / l1;
    #pragma unroll
    for (int nb = 0; nb < 8; nb++) {
        const int col = nb * 8 + 2 * kc;
        if (r0 < qlen) {
            __half2 v = __floats2half2_rn(oacc[nb][0] * inv0, oacc[nb][1] * inv0);
            *reinterpret_cast<__half2*>(
                out + (size_t)(q0 + r0) * D_EMB + h * D_HEAD + col) = v;
        }
        if (r0 + 8 < qlen) {
            __half2 v = __floats2half2_rn(oacc[nb][2] * inv1, oacc[nb][3] * inv1);
            *reinterpret_cast<__half2*>(
                out + (size_t)(q0 + r0 + 8) * D_EMB + h * D_HEAD + col) = v;
        }
    }
}

// ---------------- launcher ----------------
extern "C" void kernel_launch(void* const* d_in, const int* in_sizes, int n_in,
                              void* d_out, int out_size)
{
    const float* x     = (const float*)d_in[0];
    const void*  batch = d_in[1];
    const float* W_in  = (const float*)d_in[2];
    const float* b_in  = (const float*)d_in[3];
    const float* W_out = (const float*)d_in[4];
    const float* b_out = (const float*)d_in[5];
    float*       out   = (float*)d_out;

    __half* qkvh;  cudaGetSymbolAddress((void**)&qkvh,  g_qkvh);
    __half* attnh; cudaGetSymbolAddress((void**)&attnh, g_attnh);
    __half* xh;    cudaGetSymbolAddress((void**)&xh,    g_xh);
    __half* wih;   cudaGetSymbolAddress((void**)&wih,   g_wih);
    __half* woh;   cudaGetSymbolAddress((void**)&woh,   g_woh);

    cudaFuncSetAttribute(gemm_f16_cp<__half>,
                         cudaFuncAttributeMaxDynamicSharedMemorySize, GEMM_SMEM);
    cudaFuncSetAttribute(gemm_f16_cp<float>,
                         cudaFuncAttributeMaxDynamicSharedMemorySize, GEMM_SMEM);
    cudaFuncSetAttribute(attn_f16,
                         cudaFuncAttributeMaxDynamicSharedMemorySize, ATTN_SMEM);

    prep_kernel<<<1, 256>>>(batch);

    // fused fp16 conversion (single launch)
    {
        const int nx  = (N_TOK * D_EMB) / 4;
        const int nwi = (D_EMB * D3) / 4;
        const int nwo = (D_EMB * D_EMB) / 4;
        const int tot = nx + nwi + nwo;
        cvt_all_fp16<<<(tot + 255) / 256, 256>>>(
            (const float4*)x,     (uint2*)xh,  nx,
            (const float4*)W_in,  (uint2*)wih, nwi,
            (const float4*)W_out, (uint2*)woh, nwo);
    }

    {   // qkv = x @ W_in + b_in   (fp16 in, fp16 out)
        dim3 grid(D3 / 256, N_TOK / 128);
        gemm_f16_cp<__half><<<grid, 256, GEMM_SMEM>>>(N_TOK, D3, D_EMB, xh, wih, b_in, qkvh);
    }

    {   // segment-local fp16 tensor-core attention (TQ=128)
        dim3 grid(MAX_TILES, N_HEADS);
        attn_f16<<<grid, 256, ATTN_SMEM>>>(qkvh, attnh);
    }

    {   // out = attn @ W_out + b_out  (fp32 out)
        dim3 grid(D_EMB / 256, N_TOK / 128);
        gemm_f16_cp<float><<<grid, 256, GEMM_SMEM>>>(N_TOK, D_EMB, D_EMB, attnh, woh, b_out, out);
    }
}